// round 10
// baseline (speedup 1.0000x reference)
#include <cuda_runtime.h>
#include <cuda_fp16.h>
#include <cstdint>

#define BATCH 8
#define CIN   64
#define COUT  64
#define HH    112
#define WW    112
#define HWSZ  (HH*WW)

// ---------------- precomputed fp16 planes ----------------
// x_h: [b][y][x][c] (c contiguous: 64*2B = 128B rows)
__device__ __align__(128) __half g_x_h[BATCH * HH * WW * CIN];
// w_h: [t][o][c]
__device__ __align__(128) __half g_w_h[9 * COUT * CIN];

// ================= prep: transpose + fp16 convert =================
__global__ void xprep_kernel(const float* __restrict__ x)
{
    __shared__ float tile[CIN * 113];
    const int y = blockIdx.x, b = blockIdx.y, tid = threadIdx.x;

    for (int i = tid; i < CIN * 28; i += 256) {
        int c = i / 28, q = i - c * 28;
        float4 v = *(const float4*)&x[(((size_t)b * CIN + c) * HH + y) * WW + q * 4];
        float* d = &tile[c * 113 + q * 4];
        d[0] = v.x; d[1] = v.y; d[2] = v.z; d[3] = v.w;
    }
    __syncthreads();

    for (int i = tid; i < 896; i += 256) {
        int xx = i >> 3, cg = i & 7;
        __half h[8];
        #pragma unroll
        for (int k = 0; k < 8; k++)
            h[k] = __float2half(tile[(cg * 8 + k) * 113 + xx]);
        *(uint4*)&g_x_h[((size_t)((b * HH + y) * WW) + xx) * 64 + cg * 8] = *(uint4*)h;
    }
}

__global__ void wprep_kernel(const float* __restrict__ w)
{
    int i = blockIdx.x * 256 + threadIdx.x;
    if (i >= 9 * COUT * CIN) return;
    int c = i & 63, o = (i >> 6) & 63, t = i >> 12;
    g_w_h[(t * COUT + o) * CIN + c] = __float2half(w[o * (CIN * 9) + c * 9 + t]);
}

// ================= base-ISA async/MMA primitives =================
__device__ __forceinline__ uint32_t smem_u32(const void* p) {
    uint32_t a;
    asm("{ .reg .u64 t; cvta.to.shared.u64 t, %1; cvt.u32.u64 %0, t; }" : "=r"(a) : "l"(p));
    return a;
}
__device__ __forceinline__ void cp16(uint32_t dst, const void* src, uint32_t sz) {
    asm volatile("cp.async.cg.shared.global [%0], [%1], 16, %2;"
                 :: "r"(dst), "l"(src), "r"(sz) : "memory");
}
#define CP_COMMIT() asm volatile("cp.async.commit_group;" ::: "memory")
#define CP_WAIT0()  asm volatile("cp.async.wait_group 0;" ::: "memory")

__device__ __forceinline__ void ldmx4(uint32_t* r, uint32_t addr) {
    asm volatile("ldmatrix.sync.aligned.m8n8.x4.shared.b16 {%0,%1,%2,%3}, [%4];"
                 : "=r"(r[0]), "=r"(r[1]), "=r"(r[2]), "=r"(r[3]) : "r"(addr));
}
__device__ __forceinline__ void mma16816(float* c, const uint32_t* a,
                                         uint32_t b0, uint32_t b1) {
    asm volatile("mma.sync.aligned.m16n8k16.row.col.f32.f16.f16.f32 "
                 "{%0,%1,%2,%3}, {%4,%5,%6,%7}, {%8,%9}, {%0,%1,%2,%3};"
                 : "+f"(c[0]), "+f"(c[1]), "+f"(c[2]), "+f"(c[3])
                 : "r"(a[0]), "r"(a[1]), "r"(a[2]), "r"(a[3]), "r"(b0), "r"(b1));
}

// ================= main kernel =================
// 128 threads (4 warps), warp tile 32 (m) x 64 (n).
// smem: [0, 23040)   x tile: 180 rows x 128B (XOR-swizzled)
//       [23040, 23168) zero row
//       [23168, 39552) B double buffer: 2 x 8KB
// -> 39.6KB/CTA, 4 CTAs/SM (16 warps/SM) for latency hiding.
// epilogue reuses [0, 33792) as C[128][66] fp32.
#define X_OFF   0
#define Z_OFF   23040
#define B_OFF   23168
#define B_BUF   8192
#define SMEM_SZ 39552
#define NT      128

__global__ __launch_bounds__(NT, 4)
void rconv_mma_kernel(const int* __restrict__ mask, float* __restrict__ out)
{
    extern __shared__ __align__(128) char smem[];
    const uint32_t sb = smem_u32(smem);

    const int tid  = threadIdx.x;
    const int wid  = tid >> 5;              // 0..3  -> m-tile of 32 positions
    const int lane = tid & 31;
    const int tile = blockIdx.x;            // 0..97
    const int b    = blockIdx.y;
    const int x0   = (tile % 7) * 16;
    const int y0   = (tile / 7) * 8;

    const int m0 = wid * 32;                // warp covers positions m0..m0+31, ALL 64 outputs

    if (tid < 32) ((float*)(smem + Z_OFF))[tid] = 0.0f;

    // ---- per-thread ldmatrix geometry ----
    const int ch      = lane >> 4;          // A k-half
    const int lanerow = lane & 15;
    int  rb[2], mk[2];
    #pragma unroll
    for (int mi = 0; mi < 2; mi++) {
        int p  = m0 + mi * 16 + lanerow;    // position 0..127
        int py = p >> 4, px = p & 15;
        rb[mi] = py * 18 + px;
        mk[mi] = __ldg(&mask[(y0 + py) * WW + (x0 + px)]);
    }
    const int nlocal = (lane & 7) + ((lane >> 4) << 3);
    const int khalf  = (lane >> 3) & 1;
    int boff[4], bsw[4];
    #pragma unroll
    for (int ntp = 0; ntp < 4; ntp++) {     // 4 n16-tiles cover n=64
        int orow = ntp * 16 + nlocal;
        boff[ntp] = orow * 128;
        bsw[ntp]  = orow & 7;
    }
    const uint32_t zaddr = sb + Z_OFF;

    // ---- prologue: stage x tile + B[0] ----
    for (int i = tid; i < 1440; i += NT) {
        int r  = i >> 3;
        int j  = i & 7;
        int iy = r / 18, ix = r - iy * 18;
        int gy = y0 - 1 + iy, gx = x0 - 1 + ix;
        bool ok = (gy >= 0 && gy < HH && gx >= 0 && gx < WW);
        const __half* src = g_x_h +
            (ok ? (((size_t)((b * HH + gy) * WW + gx)) * CIN + j * 8) : 0);
        uint32_t dst = sb + X_OFF + r * 128 + ((j ^ (r & 7)) << 4);
        cp16(dst, src, ok ? 16u : 0u);
    }
    #pragma unroll
    for (int k = 0; k < 4; k++) {           // B[0]: 64 o x 8 j = 512 units
        int i = k * NT + tid;
        int o = i >> 3, j = i & 7;
        const __half* src = g_w_h + ((0 * COUT + o) * CIN + j * 8);
        uint32_t dst = sb + B_OFF + o * 128 + ((j ^ (o & 7)) << 4);
        cp16(dst, src, 16u);
    }
    CP_COMMIT();

    float C[2][8][4];                       // [m16][n8][frag]
    #pragma unroll
    for (int mi = 0; mi < 2; mi++)
        #pragma unroll
        for (int nt = 0; nt < 8; nt++)
            #pragma unroll
            for (int k = 0; k < 4; k++) C[mi][nt][k] = 0.0f;

    int buf = 0;
    #pragma unroll 1
    for (int t = 0; t < 9; t++) {
        CP_WAIT0();
        __syncthreads();

        if (t < 8) {  // prefetch B[t+1] into other buffer (overlaps compute)
            #pragma unroll
            for (int k = 0; k < 4; k++) {
                int i = k * NT + tid;
                int o = i >> 3, j = i & 7;
                const __half* src = g_w_h + (((t + 1) * COUT + o) * CIN + j * 8);
                uint32_t dst = sb + B_OFF + (buf ^ 1) * B_BUF + o * 128 + ((j ^ (o & 7)) << 4);
                cp16(dst, src, 16u);
            }
            CP_COMMIT();
        }

        const int kh   = t / 3;
        const int toff = t + kh * 15;        // kh*18 + kw
        int  r128[2], rm[2];
        bool msk[2];
        #pragma unroll
        for (int mi = 0; mi < 2; mi++) {
            int r = rb[mi] + toff;
            r128[mi] = r << 7;
            rm[mi]   = r & 7;
            msk[mi]  = (mk[mi] == t);
        }
        const uint32_t bb = sb + B_OFF + buf * B_BUF;

        #pragma unroll
        for (int kc = 0; kc < 4; kc++) {
            uint32_t A[2][4], Bv[4][4];
            #pragma unroll
            for (int mi = 0; mi < 2; mi++) {
                uint32_t sw = (uint32_t)((((kc << 1) | ch) ^ rm[mi]) << 4);
                uint32_t ah = msk[mi] ? zaddr : (sb + X_OFF + r128[mi] + sw);
                ldmx4(A[mi], ah);
            }
            #pragma unroll
            for (int ntp = 0; ntp < 4; ntp++) {
                uint32_t sw = (uint32_t)((((kc << 1) | khalf) ^ bsw[ntp]) << 4);
                ldmx4(Bv[ntp], bb + boff[ntp] + sw);
            }
            #pragma unroll
            for (int mi = 0; mi < 2; mi++)
                #pragma unroll
                for (int ntp = 0; ntp < 4; ntp++)
                    #pragma unroll
                    for (int s = 0; s < 2; s++)
                        mma16816(C[mi][ntp * 2 + s], A[mi],
                                 Bv[ntp][2 * s], Bv[ntp][2 * s + 1]);
        }
        buf ^= 1;
    }

    // ---- epilogue: C -> smem [m][o] (stride 66), then coalesced float4 stores ----
    __syncthreads();
    float* sC = (float*)smem;
    const int g   = lane >> 2;
    const int tg2 = (lane & 3) * 2;
    #pragma unroll
    for (int mi = 0; mi < 2; mi++)
        #pragma unroll
        for (int nt = 0; nt < 8; nt++) {
            int mrow = m0 + mi * 16 + g;
            int col  = nt * 8 + tg2;
            *(float2*)(sC + mrow * 66 + col)       = make_float2(C[mi][nt][0], C[mi][nt][1]);
            *(float2*)(sC + (mrow + 8) * 66 + col) = make_float2(C[mi][nt][2], C[mi][nt][3]);
        }
    __syncthreads();

    #pragma unroll
    for (int it = 0; it < 16; it++) {
        int idx = it * NT + tid;           // (o, py, q)
        int o   = idx >> 5;
        int rem = idx & 31;
        int py  = rem >> 2;
        int px  = (rem & 3) * 4;
        int mb  = py * 16 + px;
        float4 v;
        v.x = sC[(mb + 0) * 66 + o];
        v.y = sC[(mb + 1) * 66 + o];
        v.z = sC[(mb + 2) * 66 + o];
        v.w = sC[(mb + 3) * 66 + o];
        *(float4*)(out + ((size_t)(b * COUT + o)) * HWSZ + (y0 + py) * WW + (x0 + px)) = v;
    }
}

// ================= launch =================
extern "C" void kernel_launch(void* const* d_in, const int* in_sizes, int n_in,
                              void* d_out, int out_size)
{
    (void)in_sizes; (void)n_in; (void)out_size;
    const float* x    = (const float*)d_in[0];
    const float* w    = (const float*)d_in[1];
    const int*   mask = (const int*)d_in[2];
    float*       out  = (float*)d_out;

    xprep_kernel<<<dim3(HH, BATCH), 256>>>(x);
    wprep_kernel<<<(9 * COUT * CIN + 255) / 256, 256>>>(w);

    cudaFuncSetAttribute(rconv_mma_kernel,
                         cudaFuncAttributeMaxDynamicSharedMemorySize, SMEM_SZ);
    rconv_mma_kernel<<<dim3(98, BATCH), NT, SMEM_SZ>>>(mask, out);
}

// round 12
// speedup vs baseline: 1.0437x; 1.0437x over previous
#include <cuda_runtime.h>
#include <cuda_fp16.h>
#include <cstdint>

#define BATCH 8
#define CIN   64
#define COUT  64
#define HH    112
#define WW    112
#define HWSZ  (HH*WW)

// ---------------- precomputed fp16 planes ----------------
// x_h: [b][y][x][c] (c contiguous, 64*2B = 128B rows)
__device__ __align__(128) __half g_x_h[BATCH * HH * WW * CIN];
// w_h: [t][o][c]
__device__ __align__(128) __half g_w_h[9 * COUT * CIN];

// ================= fused prep: x transpose+convert AND w reorder =================
// grid (232, 8), 128 threads:
//   blockIdx.x < 224 : x-prep for (b=blockIdx.y, y=bx>>1, half=bx&1) -> 56 x-positions
//   blockIdx.x >= 224: w-prep slice (64 CTAs x 576 elements)
#define PS 114   // EVEN stride in halves -> all __half2 STS 4B-aligned

__global__ __launch_bounds__(128, 15)
void prep_kernel(const float* __restrict__ x, const float* __restrict__ w)
{
    __shared__ __align__(16) __half stile[CIN * PS];
    const int tid = threadIdx.x;
    const int bx  = blockIdx.x;
    const int b   = blockIdx.y;

    if (bx >= 224) {
        // ---- w-prep: 64 CTAs x 576 elements ----
        const int slot = (bx - 224) + 8 * b;      // 0..63
        #pragma unroll
        for (int j = 0; j < 5; j++) {
            int el = j * 128 + tid;
            if (el < 576) {
                int e = slot * 576 + el;          // 0..36863
                int c = e & 63, o = (e >> 6) & 63, t = e >> 12;
                g_w_h[(t * COUT + o) * CIN + c] =
                    __float2half(w[o * (CIN * 9) + c * 9 + t]);
            }
        }
        return;
    }

    // ---- x-prep: one (b, y, x-half) slice of 56 positions ----
    const int y    = bx >> 1;
    const int half = (bx & 1) * 56;
    const float* xb = x + ((size_t)b * CIN) * HWSZ + y * WW + half;

    // phase 1: coalesced float4 reads, convert to fp16, aligned half2 STS
    #pragma unroll
    for (int k = 0; k < 8; k++) {
        int u   = k * 128 + tid;
        int c   = u >> 4;          // 0..63
        int sub = u & 15;          // 0..15, 14 valid
        if (sub < 14) {
            float4 v = *(const float4*)&xb[(size_t)c * HWSZ + sub * 4];
            __half2 h0 = __floats2half2_rn(v.x, v.y);
            __half2 h1 = __floats2half2_rn(v.z, v.w);
            *(__half2*)&stile[c * PS + sub * 4]     = h0;   // c*PS even, sub*4 even -> 4B aligned
            *(__half2*)&stile[c * PS + sub * 4 + 2] = h1;
        }
    }
    __syncthreads();

    // phase 2: gather 8 channels per thread, coalesced uint4 STG
    const int cg = tid & 7;
    #pragma unroll
    for (int j = 0; j < 4; j++) {
        int xx = j * 16 + (tid >> 3);   // 0..63, 56 valid
        if (xx < 56) {
            __half h[8];
            #pragma unroll
            for (int k = 0; k < 8; k++)
                h[k] = stile[(cg * 8 + k) * PS + xx];
            *(uint4*)&g_x_h[((size_t)((b * HH + y) * WW) + half + xx) * CIN + cg * 8] =
                *(uint4*)h;
        }
    }
}

// ================= base-ISA async/MMA primitives =================
__device__ __forceinline__ uint32_t smem_u32(const void* p) {
    uint32_t a;
    asm("{ .reg .u64 t; cvta.to.shared.u64 t, %1; cvt.u32.u64 %0, t; }" : "=r"(a) : "l"(p));
    return a;
}
__device__ __forceinline__ void cp16(uint32_t dst, const void* src, uint32_t sz) {
    asm volatile("cp.async.cg.shared.global [%0], [%1], 16, %2;"
                 :: "r"(dst), "l"(src), "r"(sz) : "memory");
}
#define CP_COMMIT() asm volatile("cp.async.commit_group;" ::: "memory")
#define CP_WAIT0()  asm volatile("cp.async.wait_group 0;" ::: "memory")

__device__ __forceinline__ void ldmx4(uint32_t* r, uint32_t addr) {
    asm volatile("ldmatrix.sync.aligned.m8n8.x4.shared.b16 {%0,%1,%2,%3}, [%4];"
                 : "=r"(r[0]), "=r"(r[1]), "=r"(r[2]), "=r"(r[3]) : "r"(addr));
}
__device__ __forceinline__ void mma16816(float* c, const uint32_t* a,
                                         uint32_t b0, uint32_t b1) {
    asm volatile("mma.sync.aligned.m16n8k16.row.col.f32.f16.f16.f32 "
                 "{%0,%1,%2,%3}, {%4,%5,%6,%7}, {%8,%9}, {%0,%1,%2,%3};"
                 : "+f"(c[0]), "+f"(c[1]), "+f"(c[2]), "+f"(c[3])
                 : "r"(a[0]), "r"(a[1]), "r"(a[2]), "r"(a[3]), "r"(b0), "r"(b1));
}

// ================= main kernel (unchanged from R10 WIN state) =================
// 128 threads (4 warps), warp tile 32 (m) x 64 (n).
// smem: [0, 23040)   x tile: 180 rows x 128B (XOR-swizzled)
//       [23040, 23168) zero row
//       [23168, 39552) B double buffer: 2 x 8KB
// epilogue reuses [0, 33792) as C[128][66] fp32.
#define X_OFF   0
#define Z_OFF   23040
#define B_OFF   23168
#define B_BUF   8192
#define SMEM_SZ 39552
#define NT      128

__global__ __launch_bounds__(NT, 4)
void rconv_mma_kernel(const int* __restrict__ mask, float* __restrict__ out)
{
    extern __shared__ __align__(128) char smem[];
    const uint32_t sb = smem_u32(smem);

    const int tid  = threadIdx.x;
    const int wid  = tid >> 5;              // 0..3  -> m-tile of 32 positions
    const int lane = tid & 31;
    const int tile = blockIdx.x;            // 0..97
    const int b    = blockIdx.y;
    const int x0   = (tile % 7) * 16;
    const int y0   = (tile / 7) * 8;

    const int m0 = wid * 32;                // warp covers positions m0..m0+31, ALL 64 outputs

    if (tid < 32) ((float*)(smem + Z_OFF))[tid] = 0.0f;

    // ---- per-thread ldmatrix geometry ----
    const int ch      = lane >> 4;          // A k-half
    const int lanerow = lane & 15;
    int  rb[2], mk[2];
    #pragma unroll
    for (int mi = 0; mi < 2; mi++) {
        int p  = m0 + mi * 16 + lanerow;    // position 0..127
        int py = p >> 4, px = p & 15;
        rb[mi] = py * 18 + px;
        mk[mi] = __ldg(&mask[(y0 + py) * WW + (x0 + px)]);
    }
    const int nlocal = (lane & 7) + ((lane >> 4) << 3);
    const int khalf  = (lane >> 3) & 1;
    int boff[4], bsw[4];
    #pragma unroll
    for (int ntp = 0; ntp < 4; ntp++) {     // 4 n16-tiles cover n=64
        int orow = ntp * 16 + nlocal;
        boff[ntp] = orow * 128;
        bsw[ntp]  = orow & 7;
    }
    const uint32_t zaddr = sb + Z_OFF;

    // ---- prologue: stage x tile + B[0] ----
    for (int i = tid; i < 1440; i += NT) {
        int r  = i >> 3;
        int j  = i & 7;
        int iy = r / 18, ix = r - iy * 18;
        int gy = y0 - 1 + iy, gx = x0 - 1 + ix;
        bool ok = (gy >= 0 && gy < HH && gx >= 0 && gx < WW);
        const __half* src = g_x_h +
            (ok ? (((size_t)((b * HH + gy) * WW + gx)) * CIN + j * 8) : 0);
        uint32_t dst = sb + X_OFF + r * 128 + ((j ^ (r & 7)) << 4);
        cp16(dst, src, ok ? 16u : 0u);
    }
    #pragma unroll
    for (int k = 0; k < 4; k++) {           // B[0]: 64 o x 8 j = 512 units
        int i = k * NT + tid;
        int o = i >> 3, j = i & 7;
        const __half* src = g_w_h + ((0 * COUT + o) * CIN + j * 8);
        uint32_t dst = sb + B_OFF + o * 128 + ((j ^ (o & 7)) << 4);
        cp16(dst, src, 16u);
    }
    CP_COMMIT();

    float C[2][8][4];                       // [m16][n8][frag]
    #pragma unroll
    for (int mi = 0; mi < 2; mi++)
        #pragma unroll
        for (int nt = 0; nt < 8; nt++)
            #pragma unroll
            for (int k = 0; k < 4; k++) C[mi][nt][k] = 0.0f;

    int buf = 0;
    #pragma unroll 1
    for (int t = 0; t < 9; t++) {
        CP_WAIT0();
        __syncthreads();

        if (t < 8) {  // prefetch B[t+1] into other buffer (overlaps compute)
            #pragma unroll
            for (int k = 0; k < 4; k++) {
                int i = k * NT + tid;
                int o = i >> 3, j = i & 7;
                const __half* src = g_w_h + (((t + 1) * COUT + o) * CIN + j * 8);
                uint32_t dst = sb + B_OFF + (buf ^ 1) * B_BUF + o * 128 + ((j ^ (o & 7)) << 4);
                cp16(dst, src, 16u);
            }
            CP_COMMIT();
        }

        const int kh   = t / 3;
        const int toff = t + kh * 15;        // kh*18 + kw
        int  r128[2], rm[2];
        bool msk[2];
        #pragma unroll
        for (int mi = 0; mi < 2; mi++) {
            int r = rb[mi] + toff;
            r128[mi] = r << 7;
            rm[mi]   = r & 7;
            msk[mi]  = (mk[mi] == t);
        }
        const uint32_t bb = sb + B_OFF + buf * B_BUF;

        #pragma unroll
        for (int kc = 0; kc < 4; kc++) {
            uint32_t A[2][4], Bv[4][4];
            #pragma unroll
            for (int mi = 0; mi < 2; mi++) {
                uint32_t sw = (uint32_t)((((kc << 1) | ch) ^ rm[mi]) << 4);
                uint32_t ah = msk[mi] ? zaddr : (sb + X_OFF + r128[mi] + sw);
                ldmx4(A[mi], ah);
            }
            #pragma unroll
            for (int ntp = 0; ntp < 4; ntp++) {
                uint32_t sw = (uint32_t)((((kc << 1) | khalf) ^ bsw[ntp]) << 4);
                ldmx4(Bv[ntp], bb + boff[ntp] + sw);
            }
            #pragma unroll
            for (int mi = 0; mi < 2; mi++)
                #pragma unroll
                for (int ntp = 0; ntp < 4; ntp++)
                    #pragma unroll
                    for (int s = 0; s < 2; s++)
                        mma16816(C[mi][ntp * 2 + s], A[mi],
                                 Bv[ntp][2 * s], Bv[ntp][2 * s + 1]);
        }
        buf ^= 1;
    }

    // ---- epilogue: C -> smem [m][o] (stride 66), then coalesced float4 stores ----
    __syncthreads();
    float* sC = (float*)smem;
    const int g   = lane >> 2;
    const int tg2 = (lane & 3) * 2;
    #pragma unroll
    for (int mi = 0; mi < 2; mi++)
        #pragma unroll
        for (int nt = 0; nt < 8; nt++) {
            int mrow = m0 + mi * 16 + g;
            int col  = nt * 8 + tg2;
            *(float2*)(sC + mrow * 66 + col)       = make_float2(C[mi][nt][0], C[mi][nt][1]);
            *(float2*)(sC + (mrow + 8) * 66 + col) = make_float2(C[mi][nt][2], C[mi][nt][3]);
        }
    __syncthreads();

    #pragma unroll
    for (int it = 0; it < 16; it++) {
        int idx = it * NT + tid;           // (o, py, q)
        int o   = idx >> 5;
        int rem = idx & 31;
        int py  = rem >> 2;
        int px  = (rem & 3) * 4;
        int mb  = py * 16 + px;
        float4 v;
        v.x = sC[(mb + 0) * 66 + o];
        v.y = sC[(mb + 1) * 66 + o];
        v.z = sC[(mb + 2) * 66 + o];
        v.w = sC[(mb + 3) * 66 + o];
        *(float4*)(out + ((size_t)(b * COUT + o)) * HWSZ + (y0 + py) * WW + (x0 + px)) = v;
    }
}

// ================= launch =================
extern "C" void kernel_launch(void* const* d_in, const int* in_sizes, int n_in,
                              void* d_out, int out_size)
{
    (void)in_sizes; (void)n_in; (void)out_size;
    const float* x    = (const float*)d_in[0];
    const float* w    = (const float*)d_in[1];
    const int*   mask = (const int*)d_in[2];
    float*       out  = (float*)d_out;

    prep_kernel<<<dim3(232, BATCH), 128>>>(x, w);

    cudaFuncSetAttribute(rconv_mma_kernel,
                         cudaFuncAttributeMaxDynamicSharedMemorySize, SMEM_SZ);
    rconv_mma_kernel<<<dim3(98, BATCH), NT, SMEM_SZ>>>(mask, out);
}